// round 2
// baseline (speedup 1.0000x reference)
#include <cuda_runtime.h>
#include <math.h>

// Problem shape (fixed by the dataset)
#define W_ 160
#define H_ 128
#define C_ 32
#define G_ 8
#define D_ 48
#define S_ 2
#define HW_ (H_ * W_)

// Scratch (no cudaMalloc allowed)
// ref softmax, channel-packed: g_ref4[g*HW + p] = softmax over the 4 channels of group g at pixel p
__device__ float4 g_ref4[G_ * HW_];
// src features, channel-packed: g_src4[(s*G + g)*HW + p] = the 4 channels of group g at pixel p
__device__ float4 g_src4[S_ * G_ * HW_];
// Per-source rotation (row-major 3x3) and translation of proj = src_proj @ inv(ref_proj)
__device__ float g_rot[S_][9];
__device__ float g_trans[S_][3];
// Folded depth-weight MLP constants
__device__ float g_w1[G_];
__device__ float g_aff[4];  // s1, c1, w2, b2

// ---------------------------------------------------------------------------
// Prep (single fused kernel):
//  - thread (0,0): FP32 4x4 inverse + proj products + BN fold (serial, ~0.5us)
//  - threads [0, S*G*HW): transpose src features into channel-packed float4
//  - threads [S*G*HW, S*G*HW + G*HW): ref softmax into channel-packed float4
// ---------------------------------------------------------------------------
#define T1_ (S_ * G_ * HW_)
#define T2_ (T1_ + G_ * HW_)

__global__ __launch_bounds__(256) void prep_all_kernel(
    const float* __restrict__ ref_feature,
    const float* __restrict__ srcF,
    const float* __restrict__ ref_proj,
    const float* __restrict__ src_projs,
    const float* __restrict__ w1,
    const float* __restrict__ bn_gamma,
    const float* __restrict__ bn_beta,
    const float* __restrict__ bn_mean,
    const float* __restrict__ bn_var,
    const float* __restrict__ w2,
    const float* __restrict__ b2) {
    int t = blockIdx.x * blockDim.x + threadIdx.x;

    if (t == 0) {
        // FP32 Gauss-Jordan inverse with partial pivoting
        float a[4][8];
        for (int i = 0; i < 4; i++)
            for (int j = 0; j < 4; j++) {
                a[i][j] = ref_proj[i * 4 + j];
                a[i][4 + j] = (i == j) ? 1.0f : 0.0f;
            }
        for (int col = 0; col < 4; col++) {
            int piv = col;
            float best = fabsf(a[col][col]);
            for (int r = col + 1; r < 4; r++) {
                float v = fabsf(a[r][col]);
                if (v > best) { best = v; piv = r; }
            }
            if (piv != col)
                for (int j = 0; j < 8; j++) {
                    float tmp = a[col][j]; a[col][j] = a[piv][j]; a[piv][j] = tmp;
                }
            float inv = 1.0f / a[col][col];
            for (int j = 0; j < 8; j++) a[col][j] *= inv;
            for (int r = 0; r < 4; r++) {
                if (r == col) continue;
                float f = a[r][col];
                for (int j = 0; j < 8; j++) a[r][j] -= f * a[col][j];
            }
        }
        for (int s = 0; s < S_; s++) {
            const float* sp = src_projs + s * 16;
            for (int i = 0; i < 3; i++) {
                float pr[4];
                for (int j = 0; j < 4; j++) {
                    float acc = 0.0f;
                    for (int k = 0; k < 4; k++)
                        acc += sp[i * 4 + k] * a[k][4 + j];
                    pr[j] = acc;
                }
                g_rot[s][i * 3 + 0] = pr[0];
                g_rot[s][i * 3 + 1] = pr[1];
                g_rot[s][i * 3 + 2] = pr[2];
                g_trans[s][i] = pr[3];
            }
        }
        for (int g = 0; g < G_; g++) g_w1[g] = w1[g];
        float s1 = bn_gamma[0] * rsqrtf(bn_var[0] + 1e-5f);
        float c1 = bn_beta[0] - bn_mean[0] * s1;
        g_aff[0] = s1;
        g_aff[1] = c1;
        g_aff[2] = w2[0];
        g_aff[3] = b2[0];
    }

    if (t < T1_) {
        // src transpose to channel-packed
        int p = t % HW_;
        int sg = t / HW_;           // s*G + g
        int s = sg / G_;
        int g = sg % G_;
        const float* b = srcF + (s * C_ + 4 * g) * HW_ + p;
        float4 v;
        v.x = b[0];
        v.y = b[HW_];
        v.z = b[2 * HW_];
        v.w = b[3 * HW_];
        g_src4[sg * HW_ + p] = v;
    } else if (t < T2_) {
        // ref softmax, channel-packed
        int u = t - T1_;
        int p = u % HW_;
        int g = u / HW_;
        const float* b = ref_feature + (g * 4) * HW_ + p;
        float v0 = b[0], v1 = b[HW_], v2 = b[2 * HW_], v3 = b[3 * HW_];
        float m = fmaxf(fmaxf(v0, v1), fmaxf(v2, v3));
        float e0 = __expf(v0 - m), e1 = __expf(v1 - m);
        float e2 = __expf(v2 - m), e3 = __expf(v3 - m);
        float is = __fdividef(1.0f, (e0 + e1) + (e2 + e3));
        float4 o;
        o.x = e0 * is;
        o.y = e1 * is;
        o.z = e2 * is;
        o.w = e3 * is;
        g_ref4[g * HW_ + p] = o;
    }
}

// ---------------------------------------------------------------------------
// Main fused kernel: one thread per (d, h, w). Channel-packed float4 gathers:
// one LDG.128 per bilinear corner per (group, source) fetches 4 channels.
// ---------------------------------------------------------------------------
__global__ __launch_bounds__(256) void fuse_kernel(const float* __restrict__ depths,
                                                   float* __restrict__ out) {
    int t = blockIdx.x * blockDim.x + threadIdx.x;
    if (t >= D_ * HW_) return;
    int p = t % HW_;
    int d = t / HW_;
    int x = p % W_;
    int y = p / W_;
    float xf = (float)x, yf = (float)y;
    float depth = depths[d];

    // Per-source bilinear corner weights (folded with validity) and offsets
    float ew[S_][4];
    int off[S_][4];
#pragma unroll
    for (int s = 0; s < S_; s++) {
        float r00 = g_rot[s][0], r01 = g_rot[s][1], r02 = g_rot[s][2];
        float r10 = g_rot[s][3], r11 = g_rot[s][4], r12 = g_rot[s][5];
        float r20 = g_rot[s][6], r21 = g_rot[s][7], r22 = g_rot[s][8];
        float X = fmaf(fmaf(r00, xf, fmaf(r01, yf, r02)), depth, g_trans[s][0]);
        float Y = fmaf(fmaf(r10, xf, fmaf(r11, yf, r12)), depth, g_trans[s][1]);
        float Z = fmaf(fmaf(r20, xf, fmaf(r21, yf, r22)), depth, g_trans[s][2]);
        float iz = __fdividef(1.0f, Z);
        float px = X * iz;
        float py = Y * iz;
        float x0f = floorf(px), y0f = floorf(py);
        float wx = px - x0f, wy = py - y0f;
#pragma unroll
        for (int k = 0; k < 4; k++) {
            int dx = k & 1, dy = k >> 1;
            float cx = x0f + (float)dx;
            float cy = y0f + (float)dy;
            bool valid = (cx >= 0.0f) && (cx <= (float)(W_ - 1)) &&
                         (cy >= 0.0f) && (cy <= (float)(H_ - 1));
            float wt = (dx ? wx : 1.0f - wx) * (dy ? wy : 1.0f - wy);
            ew[s][k] = valid ? wt : 0.0f;
            int xi = min(max((int)cx, 0), W_ - 1);
            int yi = min(max((int)cy, 0), H_ - 1);
            off[s][k] = yi * W_ + xi;
        }
    }

    float v[S_][G_];
    float lin0 = 0.0f, lin1 = 0.0f;

#pragma unroll
    for (int g = 0; g < G_; g++) {
        float4 r = g_ref4[g * HW_ + p];
#pragma unroll
        for (int s = 0; s < S_; s++) {
            const float4* sb = g_src4 + (s * G_ + g) * HW_;
            float a0 = 0.0f, a1 = 0.0f, a2 = 0.0f, a3 = 0.0f;
#pragma unroll
            for (int k = 0; k < 4; k++) {
                float wq = ew[s][k];
                if (wq != 0.0f) {
                    float4 q = sb[off[s][k]];
                    a0 = fmaf(wq, q.x, a0);
                    a1 = fmaf(wq, q.y, a1);
                    a2 = fmaf(wq, q.z, a2);
                    a3 = fmaf(wq, q.w, a3);
                }
            }
            float m = fmaxf(fmaxf(a0, a1), fmaxf(a2, a3));
            float e0 = __expf(a0 - m), e1 = __expf(a1 - m);
            float e2 = __expf(a2 - m), e3 = __expf(a3 - m);
            float ssum = (e0 + e1) + (e2 + e3);
            float num = fmaf(e0, r.x, fmaf(e1, r.y, fmaf(e2, r.z, e3 * r.w)));
            float vv = __fdividef(num, ssum);
            v[s][g] = vv;
            if (s == 0) lin0 = fmaf(g_w1[g], vv, lin0);
            else        lin1 = fmaf(g_w1[g], vv, lin1);
        }
    }

    float s1 = g_aff[0], c1 = g_aff[1], w2c = g_aff[2], b2c = g_aff[3];
    float lin[S_] = {lin0, lin1};
    float wgt[S_];
#pragma unroll
    for (int s = 0; s < S_; s++) {
        float bn = fmaf(lin[s], s1, c1);
        float ac = fmaf(fmaxf(bn, 0.0f), w2c, b2c);
        wgt[s] = __fdividef(1.0f, 1.0f + __expf(-ac));
    }
    float iw = __fdividef(1.0f, wgt[0] + wgt[1]);
#pragma unroll
    for (int g = 0; g < G_; g++) {
        out[(g * D_ + d) * HW_ + p] =
            (wgt[0] * v[0][g] + wgt[1] * v[1][g]) * iw;
    }
}

// ---------------------------------------------------------------------------
// Launch
// ---------------------------------------------------------------------------
extern "C" void kernel_launch(void* const* d_in, const int* in_sizes, int n_in,
                              void* d_out, int out_size) {
    const float* ref_feature = (const float*)d_in[0];
    const float* src_features = (const float*)d_in[1];
    const float* ref_proj = (const float*)d_in[2];
    const float* src_projs = (const float*)d_in[3];
    const float* depth_hypos = (const float*)d_in[4];
    const float* w1 = (const float*)d_in[5];
    const float* bn_gamma = (const float*)d_in[6];
    const float* bn_beta = (const float*)d_in[7];
    const float* bn_mean = (const float*)d_in[8];
    const float* bn_var = (const float*)d_in[9];
    const float* w2 = (const float*)d_in[10];
    const float* b2 = (const float*)d_in[11];
    float* out = (float*)d_out;

    prep_all_kernel<<<(T2_ + 255) / 256, 256>>>(
        ref_feature, src_features, ref_proj, src_projs, w1, bn_gamma, bn_beta,
        bn_mean, bn_var, w2, b2);

    int n_main = D_ * HW_;
    fuse_kernel<<<(n_main + 255) / 256, 256>>>(depth_hypos, out);
}

// round 3
// speedup vs baseline: 1.0682x; 1.0682x over previous
#include <cuda_runtime.h>
#include <math.h>

// Problem shape (fixed by the dataset)
#define W_ 160
#define H_ 128
#define C_ 32
#define G_ 8
#define D_ 48
#define S_ 2
#define HW_ (H_ * W_)

#define SNAP_ 1e-5f

// Scratch (no cudaMalloc allowed)
__device__ float4 g_ref4[G_ * HW_];          // ref softmax, channel-packed
__device__ float4 g_src4[S_ * G_ * HW_];     // src features, channel-packed
__device__ float g_rot[S_][9];
__device__ float g_trans[S_][3];
__device__ float g_w1[G_];
__device__ float g_aff[4];  // s1, c1, w2, b2

// ---------------------------------------------------------------------------
// Prep (single fused kernel): params (thread 0) + src transpose + ref softmax
// ---------------------------------------------------------------------------
#define T1_ (S_ * G_ * HW_)
#define T2_ (T1_ + G_ * HW_)

__global__ __launch_bounds__(256) void prep_all_kernel(
    const float* __restrict__ ref_feature,
    const float* __restrict__ srcF,
    const float* __restrict__ ref_proj,
    const float* __restrict__ src_projs,
    const float* __restrict__ w1,
    const float* __restrict__ bn_gamma,
    const float* __restrict__ bn_beta,
    const float* __restrict__ bn_mean,
    const float* __restrict__ bn_var,
    const float* __restrict__ w2,
    const float* __restrict__ b2) {
    int t = blockIdx.x * blockDim.x + threadIdx.x;

    if (t == 0) {
        // FP32 Gauss-Jordan inverse with partial pivoting
        float a[4][8];
        for (int i = 0; i < 4; i++)
            for (int j = 0; j < 4; j++) {
                a[i][j] = ref_proj[i * 4 + j];
                a[i][4 + j] = (i == j) ? 1.0f : 0.0f;
            }
        for (int col = 0; col < 4; col++) {
            int piv = col;
            float best = fabsf(a[col][col]);
            for (int r = col + 1; r < 4; r++) {
                float v = fabsf(a[r][col]);
                if (v > best) { best = v; piv = r; }
            }
            if (piv != col)
                for (int j = 0; j < 8; j++) {
                    float tmp = a[col][j]; a[col][j] = a[piv][j]; a[piv][j] = tmp;
                }
            float inv = 1.0f / a[col][col];
            for (int j = 0; j < 8; j++) a[col][j] *= inv;
            for (int r = 0; r < 4; r++) {
                if (r == col) continue;
                float f = a[r][col];
                for (int j = 0; j < 8; j++) a[r][j] -= f * a[col][j];
            }
        }
        for (int s = 0; s < S_; s++) {
            const float* sp = src_projs + s * 16;
            for (int i = 0; i < 3; i++) {
                float pr[4];
                for (int j = 0; j < 4; j++) {
                    float acc = 0.0f;
                    for (int k = 0; k < 4; k++)
                        acc += sp[i * 4 + k] * a[k][4 + j];
                    pr[j] = acc;
                }
                g_rot[s][i * 3 + 0] = pr[0];
                g_rot[s][i * 3 + 1] = pr[1];
                g_rot[s][i * 3 + 2] = pr[2];
                g_trans[s][i] = pr[3];
            }
        }
        for (int g = 0; g < G_; g++) g_w1[g] = w1[g];
        float s1 = bn_gamma[0] * rsqrtf(bn_var[0] + 1e-5f);
        float c1 = bn_beta[0] - bn_mean[0] * s1;
        g_aff[0] = s1;
        g_aff[1] = c1;
        g_aff[2] = w2[0];
        g_aff[3] = b2[0];
    }

    if (t < T1_) {
        int p = t % HW_;
        int sg = t / HW_;           // s*G + g
        int s = sg / G_;
        int g = sg % G_;
        const float* b = srcF + (s * C_ + 4 * g) * HW_ + p;
        float4 v;
        v.x = b[0];
        v.y = b[HW_];
        v.z = b[2 * HW_];
        v.w = b[3 * HW_];
        g_src4[sg * HW_ + p] = v;
    } else if (t < T2_) {
        int u = t - T1_;
        int p = u % HW_;
        int g = u / HW_;
        const float* b = ref_feature + (g * 4) * HW_ + p;
        float e0 = __expf(b[0]);
        float e1 = __expf(b[HW_]);
        float e2 = __expf(b[2 * HW_]);
        float e3 = __expf(b[3 * HW_]);
        float is = __fdividef(1.0f, (e0 + e1) + (e2 + e3));
        float4 o;
        o.x = e0 * is;
        o.y = e1 * is;
        o.z = e2 * is;
        o.w = e3 * is;
        g_ref4[g * HW_ + p] = o;
    }
}

// ---------------------------------------------------------------------------
// Main fused kernel: one thread per (d, h, w). Bilinear weights snapped to
// {0,1} when within SNAP_ -> zero-weight corners are skipped (warp-uniform:
// W divisible by 32 so each warp shares y and d).
// ---------------------------------------------------------------------------
__global__ __launch_bounds__(256) void fuse_kernel(const float* __restrict__ depths,
                                                   float* __restrict__ out) {
    int t = blockIdx.x * blockDim.x + threadIdx.x;
    if (t >= D_ * HW_) return;
    int p = t % HW_;
    int d = t / HW_;
    int x = p % W_;
    int y = p / W_;
    float xf = (float)x, yf = (float)y;
    float depth = depths[d];

    // Per-source bilinear corner weights (folded with validity) and offsets
    float ew[S_][4];
    int off[S_][4];
#pragma unroll
    for (int s = 0; s < S_; s++) {
        float r00 = g_rot[s][0], r01 = g_rot[s][1], r02 = g_rot[s][2];
        float r10 = g_rot[s][3], r11 = g_rot[s][4], r12 = g_rot[s][5];
        float r20 = g_rot[s][6], r21 = g_rot[s][7], r22 = g_rot[s][8];
        float X = fmaf(fmaf(r00, xf, fmaf(r01, yf, r02)), depth, g_trans[s][0]);
        float Y = fmaf(fmaf(r10, xf, fmaf(r11, yf, r12)), depth, g_trans[s][1]);
        float Z = fmaf(fmaf(r20, xf, fmaf(r21, yf, r22)), depth, g_trans[s][2]);
        float iz = __fdividef(1.0f, Z);
        float px = X * iz;
        float py = Y * iz;
        float x0f = floorf(px), y0f = floorf(py);
        float wx = px - x0f, wy = py - y0f;
        // Snap near-integer sample coords: kills zero-weight corners exactly.
        if (wx < SNAP_) { wx = 0.0f; }
        else if (wx > 1.0f - SNAP_) { wx = 0.0f; x0f += 1.0f; }
        if (wy < SNAP_) { wy = 0.0f; }
        else if (wy > 1.0f - SNAP_) { wy = 0.0f; y0f += 1.0f; }
#pragma unroll
        for (int k = 0; k < 4; k++) {
            int dx = k & 1, dy = k >> 1;
            float cx = x0f + (float)dx;
            float cy = y0f + (float)dy;
            bool valid = (cx >= 0.0f) && (cx <= (float)(W_ - 1)) &&
                         (cy >= 0.0f) && (cy <= (float)(H_ - 1));
            float wt = (dx ? wx : 1.0f - wx) * (dy ? wy : 1.0f - wy);
            ew[s][k] = valid ? wt : 0.0f;
            int xi = min(max((int)cx, 0), W_ - 1);
            int yi = min(max((int)cy, 0), H_ - 1);
            off[s][k] = yi * W_ + xi;
        }
    }

    float v[S_][G_];
    float lin0 = 0.0f, lin1 = 0.0f;

#pragma unroll
    for (int g = 0; g < G_; g++) {
        float4 r = g_ref4[g * HW_ + p];
#pragma unroll
        for (int s = 0; s < S_; s++) {
            const float4* sb = g_src4 + (s * G_ + g) * HW_;
            float a0 = 0.0f, a1 = 0.0f, a2 = 0.0f, a3 = 0.0f;
#pragma unroll
            for (int k = 0; k < 4; k++) {
                float wq = ew[s][k];
                if (wq != 0.0f) {
                    float4 q = sb[off[s][k]];
                    a0 = fmaf(wq, q.x, a0);
                    a1 = fmaf(wq, q.y, a1);
                    a2 = fmaf(wq, q.z, a2);
                    a3 = fmaf(wq, q.w, a3);
                }
            }
            // softmax(a) dot r  (no max-shift: |a| is small, exp2 safe)
            float e0 = __expf(a0), e1 = __expf(a1);
            float e2 = __expf(a2), e3 = __expf(a3);
            float ssum = (e0 + e1) + (e2 + e3);
            float num = fmaf(e0, r.x, fmaf(e1, r.y, fmaf(e2, r.z, e3 * r.w)));
            float vv = __fdividef(num, ssum);
            v[s][g] = vv;
            if (s == 0) lin0 = fmaf(g_w1[g], vv, lin0);
            else        lin1 = fmaf(g_w1[g], vv, lin1);
        }
    }

    float s1 = g_aff[0], c1 = g_aff[1], w2c = g_aff[2], b2c = g_aff[3];
    float lin[S_] = {lin0, lin1};
    float wgt[S_];
#pragma unroll
    for (int s = 0; s < S_; s++) {
        float bn = fmaf(lin[s], s1, c1);
        float ac = fmaf(fmaxf(bn, 0.0f), w2c, b2c);
        wgt[s] = __fdividef(1.0f, 1.0f + __expf(-ac));
    }
    float iw = __fdividef(1.0f, wgt[0] + wgt[1]);
#pragma unroll
    for (int g = 0; g < G_; g++) {
        out[(g * D_ + d) * HW_ + p] =
            (wgt[0] * v[0][g] + wgt[1] * v[1][g]) * iw;
    }
}

// ---------------------------------------------------------------------------
// Launch
// ---------------------------------------------------------------------------
extern "C" void kernel_launch(void* const* d_in, const int* in_sizes, int n_in,
                              void* d_out, int out_size) {
    const float* ref_feature = (const float*)d_in[0];
    const float* src_features = (const float*)d_in[1];
    const float* ref_proj = (const float*)d_in[2];
    const float* src_projs = (const float*)d_in[3];
    const float* depth_hypos = (const float*)d_in[4];
    const float* w1 = (const float*)d_in[5];
    const float* bn_gamma = (const float*)d_in[6];
    const float* bn_beta = (const float*)d_in[7];
    const float* bn_mean = (const float*)d_in[8];
    const float* bn_var = (const float*)d_in[9];
    const float* w2 = (const float*)d_in[10];
    const float* b2 = (const float*)d_in[11];
    float* out = (float*)d_out;

    prep_all_kernel<<<(T2_ + 255) / 256, 256>>>(
        ref_feature, src_features, ref_proj, src_projs, w1, bn_gamma, bn_beta,
        bn_mean, bn_var, w2, b2);

    int n_main = D_ * HW_;
    fuse_kernel<<<(n_main + 255) / 256, 256>>>(depth_hypos, out);
}

// round 4
// speedup vs baseline: 1.7698x; 1.6569x over previous
#include <cuda_runtime.h>
#include <math.h>

// Problem shape (fixed by the dataset)
#define W_ 160
#define H_ 128
#define C_ 32
#define G_ 8
#define D_ 48
#define S_ 2
#define HW_ (H_ * W_)

#define SNAP_ 3e-5f
#define BPTS_ 128  // points per block (block = 256 thr = 2 group-halves x 128 pts)

// Scratch (no cudaMalloc allowed)
__device__ float4 g_ref4[G_ * HW_];          // ref softmax, channel-packed
__device__ float4 g_src4[S_ * G_ * HW_];     // src features, channel-packed
__device__ float g_rot[S_][9];
__device__ float g_trans[S_][3];
__device__ float g_w1[G_];
__device__ float g_aff[4];  // s1, c1, w2, b2

// ---------------------------------------------------------------------------
// Prep (single fused kernel): params (thread 0) + src transpose + ref softmax
// ---------------------------------------------------------------------------
#define T1_ (S_ * G_ * HW_)
#define T2_ (T1_ + G_ * HW_)

__global__ __launch_bounds__(256) void prep_all_kernel(
    const float* __restrict__ ref_feature,
    const float* __restrict__ srcF,
    const float* __restrict__ ref_proj,
    const float* __restrict__ src_projs,
    const float* __restrict__ w1,
    const float* __restrict__ bn_gamma,
    const float* __restrict__ bn_beta,
    const float* __restrict__ bn_mean,
    const float* __restrict__ bn_var,
    const float* __restrict__ w2,
    const float* __restrict__ b2) {
    int t = blockIdx.x * blockDim.x + threadIdx.x;

    if (t == 0) {
        float a[4][8];
        for (int i = 0; i < 4; i++)
            for (int j = 0; j < 4; j++) {
                a[i][j] = ref_proj[i * 4 + j];
                a[i][4 + j] = (i == j) ? 1.0f : 0.0f;
            }
        for (int col = 0; col < 4; col++) {
            int piv = col;
            float best = fabsf(a[col][col]);
            for (int r = col + 1; r < 4; r++) {
                float v = fabsf(a[r][col]);
                if (v > best) { best = v; piv = r; }
            }
            if (piv != col)
                for (int j = 0; j < 8; j++) {
                    float tmp = a[col][j]; a[col][j] = a[piv][j]; a[piv][j] = tmp;
                }
            float inv = 1.0f / a[col][col];
            for (int j = 0; j < 8; j++) a[col][j] *= inv;
            for (int r = 0; r < 4; r++) {
                if (r == col) continue;
                float f = a[r][col];
                for (int j = 0; j < 8; j++) a[r][j] -= f * a[col][j];
            }
        }
        for (int s = 0; s < S_; s++) {
            const float* sp = src_projs + s * 16;
            for (int i = 0; i < 3; i++) {
                float pr[4];
                for (int j = 0; j < 4; j++) {
                    float acc = 0.0f;
                    for (int k = 0; k < 4; k++)
                        acc += sp[i * 4 + k] * a[k][4 + j];
                    pr[j] = acc;
                }
                g_rot[s][i * 3 + 0] = pr[0];
                g_rot[s][i * 3 + 1] = pr[1];
                g_rot[s][i * 3 + 2] = pr[2];
                g_trans[s][i] = pr[3];
            }
        }
        for (int g = 0; g < G_; g++) g_w1[g] = w1[g];
        float s1 = bn_gamma[0] * rsqrtf(bn_var[0] + 1e-5f);
        float c1 = bn_beta[0] - bn_mean[0] * s1;
        g_aff[0] = s1;
        g_aff[1] = c1;
        g_aff[2] = w2[0];
        g_aff[3] = b2[0];
    }

    if (t < T1_) {
        int p = t % HW_;
        int sg = t / HW_;
        int s = sg / G_;
        int g = sg % G_;
        const float* b = srcF + (s * C_ + 4 * g) * HW_ + p;
        float4 v;
        v.x = b[0];
        v.y = b[HW_];
        v.z = b[2 * HW_];
        v.w = b[3 * HW_];
        g_src4[sg * HW_ + p] = v;
    } else if (t < T2_) {
        int u = t - T1_;
        int p = u % HW_;
        int g = u / HW_;
        const float* b = ref_feature + (g * 4) * HW_ + p;
        float e0 = __expf(b[0]);
        float e1 = __expf(b[HW_]);
        float e2 = __expf(b[2 * HW_]);
        float e3 = __expf(b[3 * HW_]);
        float is = __fdividef(1.0f, (e0 + e1) + (e2 + e3));
        float4 o;
        o.x = e0 * is;
        o.y = e1 * is;
        o.z = e2 * is;
        o.w = e3 * is;
        g_ref4[g * HW_ + p] = o;
    }
}

// ---------------------------------------------------------------------------
// Main fused kernel.
// Block = 256 threads: warps 0-3 -> group-half 0 (groups 0..3) for 128 points,
// warps 4-7 -> group-half 1 (groups 4..7) for the SAME 128 points.
// wy is warp-uniform (py independent of x); a single uniform branch selects a
// bottom-row-free fast loop. Loads use clamped-safe offsets + folded weights,
// so no per-lane guards anywhere.
// ---------------------------------------------------------------------------
__global__ __launch_bounds__(256, 4) void fuse_kernel(const float* __restrict__ depths,
                                                      float* __restrict__ out) {
    __shared__ float s_lin[2][BPTS_][2];  // [half][point][src]

    int l = threadIdx.x & (BPTS_ - 1);    // point within block
    int h = threadIdx.x >> 7;             // group half (warp-uniform)
    int idx = blockIdx.x * BPTS_ + l;     // global point id in [0, D*HW)
    int p = idx % HW_;
    int d = idx / HW_;
    int x = p % W_;
    int y = p / W_;
    float xf = (float)x, yf = (float)y;
    float depth = depths[d];

    // Per-source geometry: base offset, step-x, step-y, 4 folded weights, wy
    int off0[S_], dx[S_], dy[S_];
    float w00[S_], w01[S_], w10[S_], w11[S_];
    float wys[S_];
#pragma unroll
    for (int s = 0; s < S_; s++) {
        float X = fmaf(fmaf(g_rot[s][0], xf, fmaf(g_rot[s][1], yf, g_rot[s][2])), depth, g_trans[s][0]);
        float Y = fmaf(fmaf(g_rot[s][3], xf, fmaf(g_rot[s][4], yf, g_rot[s][5])), depth, g_trans[s][1]);
        float Z = fmaf(fmaf(g_rot[s][6], xf, fmaf(g_rot[s][7], yf, g_rot[s][8])), depth, g_trans[s][2]);
        float iz = __fdividef(1.0f, Z);
        float px = X * iz;
        float py = Y * iz;
        float x0f = floorf(px), y0f = floorf(py);
        float wx = px - x0f, wy = py - y0f;
        if (wx < SNAP_) { wx = 0.0f; }
        else if (wx > 1.0f - SNAP_) { wx = 0.0f; x0f += 1.0f; }
        if (wy < SNAP_) { wy = 0.0f; }
        else if (wy > 1.0f - SNAP_) { wy = 0.0f; y0f += 1.0f; }
        // validity flags folded into weights
        float vx0 = (x0f >= 0.0f && x0f <= (float)(W_ - 1)) ? 1.0f : 0.0f;
        float vx1 = (x0f + 1.0f >= 0.0f && x0f + 1.0f <= (float)(W_ - 1)) ? 1.0f : 0.0f;
        float vy0 = (y0f >= 0.0f && y0f <= (float)(H_ - 1)) ? 1.0f : 0.0f;
        float vy1 = (y0f + 1.0f >= 0.0f && y0f + 1.0f <= (float)(H_ - 1)) ? 1.0f : 0.0f;
        float wl = (1.0f - wx) * vx0, wr = wx * vx1;
        float wt = (1.0f - wy) * vy0, wb = wy * vy1;
        w00[s] = wl * wt; w01[s] = wr * wt;
        w10[s] = wl * wb; w11[s] = wr * wb;
        int xi0 = min(max((int)x0f, 0), W_ - 1);
        int yi0 = min(max((int)y0f, 0), H_ - 1);
        int xi1 = min(max((int)x0f + 1, 0), W_ - 1);
        int yi1 = min(max((int)y0f + 1, 0), H_ - 1);
        off0[s] = yi0 * W_ + xi0;
        dx[s] = xi1 - xi0;        // 0 or 1
        dy[s] = (yi1 - yi0) * W_; // 0 or W
        wys[s] = wy;
    }

    float v[S_][4];
    float lin0 = 0.0f, lin1 = 0.0f;
    int gbase = h * 4;
    bool bottom = (wys[0] + wys[1]) > 0.0f;  // warp-uniform

    if (!bottom) {
#pragma unroll
        for (int j = 0; j < 4; j++) {
            int g = gbase + j;
            float4 r = g_ref4[g * HW_ + p];
#pragma unroll
            for (int s = 0; s < S_; s++) {
                const float4* sb = g_src4 + (s * G_ + g) * HW_ + off0[s];
                float4 qa = sb[0];
                float4 qb = sb[dx[s]];
                float a0 = fmaf(w00[s], qa.x, w01[s] * qb.x);
                float a1 = fmaf(w00[s], qa.y, w01[s] * qb.y);
                float a2 = fmaf(w00[s], qa.z, w01[s] * qb.z);
                float a3 = fmaf(w00[s], qa.w, w01[s] * qb.w);
                float e0 = __expf(a0), e1 = __expf(a1);
                float e2 = __expf(a2), e3 = __expf(a3);
                float ssum = (e0 + e1) + (e2 + e3);
                float num = fmaf(e0, r.x, fmaf(e1, r.y, fmaf(e2, r.z, e3 * r.w)));
                float vv = __fdividef(num, ssum);
                v[s][j] = vv;
                if (s == 0) lin0 = fmaf(g_w1[g], vv, lin0);
                else        lin1 = fmaf(g_w1[g], vv, lin1);
            }
        }
    } else {
#pragma unroll
        for (int j = 0; j < 4; j++) {
            int g = gbase + j;
            float4 r = g_ref4[g * HW_ + p];
#pragma unroll
            for (int s = 0; s < S_; s++) {
                const float4* sb = g_src4 + (s * G_ + g) * HW_ + off0[s];
                float4 qa = sb[0];
                float4 qb = sb[dx[s]];
                float4 qc = sb[dy[s]];
                float4 qd = sb[dy[s] + dx[s]];
                float a0 = fmaf(w00[s], qa.x, w01[s] * qb.x);
                float a1 = fmaf(w00[s], qa.y, w01[s] * qb.y);
                float a2 = fmaf(w00[s], qa.z, w01[s] * qb.z);
                float a3 = fmaf(w00[s], qa.w, w01[s] * qb.w);
                a0 = fmaf(w10[s], qc.x, fmaf(w11[s], qd.x, a0));
                a1 = fmaf(w10[s], qc.y, fmaf(w11[s], qd.y, a1));
                a2 = fmaf(w10[s], qc.z, fmaf(w11[s], qd.z, a2));
                a3 = fmaf(w10[s], qc.w, fmaf(w11[s], qd.w, a3));
                float e0 = __expf(a0), e1 = __expf(a1);
                float e2 = __expf(a2), e3 = __expf(a3);
                float ssum = (e0 + e1) + (e2 + e3);
                float num = fmaf(e0, r.x, fmaf(e1, r.y, fmaf(e2, r.z, e3 * r.w)));
                float vv = __fdividef(num, ssum);
                v[s][j] = vv;
                if (s == 0) lin0 = fmaf(g_w1[g], vv, lin0);
                else        lin1 = fmaf(g_w1[g], vv, lin1);
            }
        }
    }

    // Exchange partial lin sums across the two group-halves
    s_lin[h][l][0] = lin0;
    s_lin[h][l][1] = lin1;
    __syncthreads();
    float L0 = s_lin[0][l][0] + s_lin[1][l][0];
    float L1 = s_lin[0][l][1] + s_lin[1][l][1];

    float s1 = g_aff[0], c1 = g_aff[1], w2c = g_aff[2], b2c = g_aff[3];
    float bn0 = fmaf(L0, s1, c1);
    float bn1 = fmaf(L1, s1, c1);
    float ac0 = fmaf(fmaxf(bn0, 0.0f), w2c, b2c);
    float ac1 = fmaf(fmaxf(bn1, 0.0f), w2c, b2c);
    float wgt0 = __fdividef(1.0f, 1.0f + __expf(-ac0));
    float wgt1 = __fdividef(1.0f, 1.0f + __expf(-ac1));
    float iw = __fdividef(1.0f, wgt0 + wgt1);

#pragma unroll
    for (int j = 0; j < 4; j++) {
        int g = gbase + j;
        out[(g * D_ + d) * HW_ + p] = (wgt0 * v[0][j] + wgt1 * v[1][j]) * iw;
    }
}

// ---------------------------------------------------------------------------
// Launch
// ---------------------------------------------------------------------------
extern "C" void kernel_launch(void* const* d_in, const int* in_sizes, int n_in,
                              void* d_out, int out_size) {
    const float* ref_feature = (const float*)d_in[0];
    const float* src_features = (const float*)d_in[1];
    const float* ref_proj = (const float*)d_in[2];
    const float* src_projs = (const float*)d_in[3];
    const float* depth_hypos = (const float*)d_in[4];
    const float* w1 = (const float*)d_in[5];
    const float* bn_gamma = (const float*)d_in[6];
    const float* bn_beta = (const float*)d_in[7];
    const float* bn_mean = (const float*)d_in[8];
    const float* bn_var = (const float*)d_in[9];
    const float* w2 = (const float*)d_in[10];
    const float* b2 = (const float*)d_in[11];
    float* out = (float*)d_out;

    prep_all_kernel<<<(T2_ + 255) / 256, 256>>>(
        ref_feature, src_features, ref_proj, src_projs, w1, bn_gamma, bn_beta,
        bn_mean, bn_var, w2, b2);

    int n_blocks = (D_ * HW_) / BPTS_;
    fuse_kernel<<<n_blocks, 256>>>(depth_hypos, out);
}

// round 5
// speedup vs baseline: 1.9148x; 1.0819x over previous
#include <cuda_runtime.h>
#include <math.h>

// Problem shape (fixed by the dataset)
#define W_ 160
#define H_ 128
#define C_ 32
#define G_ 8
#define D_ 48
#define S_ 2
#define HW_ (H_ * W_)

#define SNAP_ 3e-5f
#define LOG2E_ 1.44269504088896340736f

// Scratch (no cudaMalloc allowed)
__device__ float4 g_ref4[G_ * HW_];          // ref softmax, channel-packed
__device__ float4 g_src4[S_ * G_ * HW_];     // src features, channel-packed
__device__ float g_rot[S_][9];
__device__ float g_trans[S_][3];
__device__ float g_w1[G_];
__device__ float g_aff[4];  // s1, c1, w2, b2

typedef unsigned long long u64;

__device__ __forceinline__ float ex2f(float x) {
    float y; asm("ex2.approx.f32 %0, %1;" : "=f"(y) : "f"(x)); return y;
}
__device__ __forceinline__ u64 pk2(float a, float b) {
    u64 r; asm("mov.b64 %0, {%1, %2};" : "=l"(r) : "f"(a), "f"(b)); return r;
}
__device__ __forceinline__ void upk2(u64 v, float& a, float& b) {
    asm("mov.b64 {%0, %1}, %2;" : "=f"(a), "=f"(b) : "l"(v));
}
__device__ __forceinline__ u64 fma2(u64 a, u64 b, u64 c) {
    u64 r; asm("fma.rn.f32x2 %0, %1, %2, %3;" : "=l"(r) : "l"(a), "l"(b), "l"(c)); return r;
}
__device__ __forceinline__ u64 mul2(u64 a, u64 b) {
    u64 r; asm("mul.rn.f32x2 %0, %1, %2;" : "=l"(r) : "l"(a), "l"(b)); return r;
}

// ---------------------------------------------------------------------------
// Prep (single fused kernel): params (thread 0) + src transpose + ref softmax
// ---------------------------------------------------------------------------
#define T1_ (S_ * G_ * HW_)
#define T2_ (T1_ + G_ * HW_)

__global__ __launch_bounds__(256) void prep_all_kernel(
    const float* __restrict__ ref_feature,
    const float* __restrict__ srcF,
    const float* __restrict__ ref_proj,
    const float* __restrict__ src_projs,
    const float* __restrict__ w1,
    const float* __restrict__ bn_gamma,
    const float* __restrict__ bn_beta,
    const float* __restrict__ bn_mean,
    const float* __restrict__ bn_var,
    const float* __restrict__ w2,
    const float* __restrict__ b2) {
    int t = blockIdx.x * blockDim.x + threadIdx.x;

    if (t == 0) {
        float a[4][8];
        for (int i = 0; i < 4; i++)
            for (int j = 0; j < 4; j++) {
                a[i][j] = ref_proj[i * 4 + j];
                a[i][4 + j] = (i == j) ? 1.0f : 0.0f;
            }
        for (int col = 0; col < 4; col++) {
            int piv = col;
            float best = fabsf(a[col][col]);
            for (int r = col + 1; r < 4; r++) {
                float v = fabsf(a[r][col]);
                if (v > best) { best = v; piv = r; }
            }
            if (piv != col)
                for (int j = 0; j < 8; j++) {
                    float tmp = a[col][j]; a[col][j] = a[piv][j]; a[piv][j] = tmp;
                }
            float inv = 1.0f / a[col][col];
            for (int j = 0; j < 8; j++) a[col][j] *= inv;
            for (int r = 0; r < 4; r++) {
                if (r == col) continue;
                float f = a[r][col];
                for (int j = 0; j < 8; j++) a[r][j] -= f * a[col][j];
            }
        }
        for (int s = 0; s < S_; s++) {
            const float* sp = src_projs + s * 16;
            for (int i = 0; i < 3; i++) {
                float pr[4];
                for (int j = 0; j < 4; j++) {
                    float acc = 0.0f;
                    for (int k = 0; k < 4; k++)
                        acc += sp[i * 4 + k] * a[k][4 + j];
                    pr[j] = acc;
                }
                g_rot[s][i * 3 + 0] = pr[0];
                g_rot[s][i * 3 + 1] = pr[1];
                g_rot[s][i * 3 + 2] = pr[2];
                g_trans[s][i] = pr[3];
            }
        }
        for (int g = 0; g < G_; g++) g_w1[g] = w1[g];
        float s1 = bn_gamma[0] * rsqrtf(bn_var[0] + 1e-5f);
        float c1 = bn_beta[0] - bn_mean[0] * s1;
        g_aff[0] = s1;
        g_aff[1] = c1;
        g_aff[2] = w2[0];
        g_aff[3] = b2[0];
    }

    if (t < T1_) {
        int p = t % HW_;
        int sg = t / HW_;
        int s = sg / G_;
        int g = sg % G_;
        const float* b = srcF + (s * C_ + 4 * g) * HW_ + p;
        float4 v;
        v.x = b[0];
        v.y = b[HW_];
        v.z = b[2 * HW_];
        v.w = b[3 * HW_];
        g_src4[sg * HW_ + p] = v;
    } else if (t < T2_) {
        int u = t - T1_;
        int p = u % HW_;
        int g = u / HW_;
        const float* b = ref_feature + (g * 4) * HW_ + p;
        float e0 = __expf(b[0]);
        float e1 = __expf(b[HW_]);
        float e2 = __expf(b[2 * HW_]);
        float e3 = __expf(b[3 * HW_]);
        float is = __fdividef(1.0f, (e0 + e1) + (e2 + e3));
        float4 o;
        o.x = e0 * is;
        o.y = e1 * is;
        o.z = e2 * is;
        o.w = e3 * is;
        g_ref4[g * HW_ + p] = o;
    }
}

// ---------------------------------------------------------------------------
// Main fused kernel.
// Grid (W/32, H/4, D); block (32, 8): tx = x-lane, ty&3 = row in 4-row tile,
// ty>>2 = group half. No integer division anywhere. Bilinear weights folded
// with validity AND log2(e), so the softmax exp is a bare ex2. Corner blends
// run on the packed f32x2 pipe.
// ---------------------------------------------------------------------------
__global__ __launch_bounds__(256, 4) void fuse_kernel(const float* __restrict__ depths,
                                                      float* __restrict__ out) {
    __shared__ float s_lin[2][4][32][2];  // [half][row][lane][src]

    int tx = threadIdx.x;                 // 0..31, x within chunk
    int ty = threadIdx.y;                 // 0..7
    int row = ty & 3;
    int h = ty >> 2;                      // group half (warp-uniform)
    int x = blockIdx.x * 32 + tx;
    int y = blockIdx.y * 4 + row;
    int d = blockIdx.z;
    int p = y * W_ + x;
    float xf = (float)x, yf = (float)y;
    float depth = __ldg(depths + d);

    // Per-source geometry
    int off0[S_], dxs[S_], dys[S_];
    u64 w00p[S_], w01p[S_], w10p[S_], w11p[S_];
    float wys[S_];
#pragma unroll
    for (int s = 0; s < S_; s++) {
        float X = fmaf(fmaf(g_rot[s][0], xf, fmaf(g_rot[s][1], yf, g_rot[s][2])), depth, g_trans[s][0]);
        float Y = fmaf(fmaf(g_rot[s][3], xf, fmaf(g_rot[s][4], yf, g_rot[s][5])), depth, g_trans[s][1]);
        float Z = fmaf(fmaf(g_rot[s][6], xf, fmaf(g_rot[s][7], yf, g_rot[s][8])), depth, g_trans[s][2]);
        float iz = __fdividef(1.0f, Z);
        float px = X * iz;
        float py = Y * iz;
        float x0f = floorf(px), y0f = floorf(py);
        float wx = px - x0f, wy = py - y0f;
        if (wx < SNAP_) { wx = 0.0f; }
        else if (wx > 1.0f - SNAP_) { wx = 0.0f; x0f += 1.0f; }
        if (wy < SNAP_) { wy = 0.0f; }
        else if (wy > 1.0f - SNAP_) { wy = 0.0f; y0f += 1.0f; }
        float vx0 = (x0f >= 0.0f && x0f <= (float)(W_ - 1)) ? LOG2E_ : 0.0f;
        float vx1 = (x0f + 1.0f >= 0.0f && x0f + 1.0f <= (float)(W_ - 1)) ? LOG2E_ : 0.0f;
        float vy0 = (y0f >= 0.0f && y0f <= (float)(H_ - 1)) ? 1.0f : 0.0f;
        float vy1 = (y0f + 1.0f >= 0.0f && y0f + 1.0f <= (float)(H_ - 1)) ? 1.0f : 0.0f;
        float wl = (1.0f - wx) * vx0, wr = wx * vx1;   // include log2e
        float wt = (1.0f - wy) * vy0, wb = wy * vy1;
        float w00 = wl * wt, w01 = wr * wt;
        float w10 = wl * wb, w11 = wr * wb;
        w00p[s] = pk2(w00, w00);
        w01p[s] = pk2(w01, w01);
        w10p[s] = pk2(w10, w10);
        w11p[s] = pk2(w11, w11);
        int xi0 = min(max((int)x0f, 0), W_ - 1);
        int yi0 = min(max((int)y0f, 0), H_ - 1);
        int xi1 = min(max((int)x0f + 1, 0), W_ - 1);
        int yi1 = min(max((int)y0f + 1, 0), H_ - 1);
        off0[s] = yi0 * W_ + xi0;
        dxs[s] = xi1 - xi0;          // 0 or 1
        dys[s] = (yi1 - yi0) * W_;   // 0 or W
        wys[s] = wy;
    }

    float v[S_][4];
    float lin0 = 0.0f, lin1 = 0.0f;
    int gbase = h * 4;
    bool bottom = (wys[0] + wys[1]) > 0.0f;  // warp-uniform

    const ulonglong2* sb0 = (const ulonglong2*)(g_src4 + (0 * G_ + gbase) * HW_ + off0[0]);
    const ulonglong2* sb1 = (const ulonglong2*)(g_src4 + (1 * G_ + gbase) * HW_ + off0[1]);
    const float4* rp = g_ref4 + gbase * HW_ + p;

    if (!bottom) {
#pragma unroll
        for (int j = 0; j < 4; j++) {
            float4 r = rp[j * HW_];
#pragma unroll
            for (int s = 0; s < S_; s++) {
                const ulonglong2* sb = (s == 0 ? sb0 : sb1) + j * HW_;
                ulonglong2 qa = sb[0];
                ulonglong2 qb = sb[dxs[s]];
                u64 a01 = fma2(w00p[s], qa.x, mul2(w01p[s], qb.x));
                u64 a23 = fma2(w00p[s], qa.y, mul2(w01p[s], qb.y));
                float a0, a1, a2, a3;
                upk2(a01, a0, a1);
                upk2(a23, a2, a3);
                float e0 = ex2f(a0), e1 = ex2f(a1);
                float e2 = ex2f(a2), e3 = ex2f(a3);
                float ssum = (e0 + e1) + (e2 + e3);
                float num = fmaf(e0, r.x, fmaf(e1, r.y, fmaf(e2, r.z, e3 * r.w)));
                float vv = __fdividef(num, ssum);
                v[s][j] = vv;
                if (s == 0) lin0 = fmaf(g_w1[gbase + j], vv, lin0);
                else        lin1 = fmaf(g_w1[gbase + j], vv, lin1);
            }
        }
    } else {
#pragma unroll
        for (int j = 0; j < 4; j++) {
            float4 r = rp[j * HW_];
#pragma unroll
            for (int s = 0; s < S_; s++) {
                const ulonglong2* sb = (s == 0 ? sb0 : sb1) + j * HW_;
                ulonglong2 qa = sb[0];
                ulonglong2 qb = sb[dxs[s]];
                ulonglong2 qc = sb[dys[s]];
                ulonglong2 qd = sb[dys[s] + dxs[s]];
                u64 a01 = fma2(w00p[s], qa.x, mul2(w01p[s], qb.x));
                u64 a23 = fma2(w00p[s], qa.y, mul2(w01p[s], qb.y));
                a01 = fma2(w10p[s], qc.x, fma2(w11p[s], qd.x, a01));
                a23 = fma2(w10p[s], qc.y, fma2(w11p[s], qd.y, a23));
                float a0, a1, a2, a3;
                upk2(a01, a0, a1);
                upk2(a23, a2, a3);
                float e0 = ex2f(a0), e1 = ex2f(a1);
                float e2 = ex2f(a2), e3 = ex2f(a3);
                float ssum = (e0 + e1) + (e2 + e3);
                float num = fmaf(e0, r.x, fmaf(e1, r.y, fmaf(e2, r.z, e3 * r.w)));
                float vv = __fdividef(num, ssum);
                v[s][j] = vv;
                if (s == 0) lin0 = fmaf(g_w1[gbase + j], vv, lin0);
                else        lin1 = fmaf(g_w1[gbase + j], vv, lin1);
            }
        }
    }

    // Exchange partial lin sums across the two group-halves
    s_lin[h][row][tx][0] = lin0;
    s_lin[h][row][tx][1] = lin1;
    __syncthreads();
    float L0 = s_lin[0][row][tx][0] + s_lin[1][row][tx][0];
    float L1 = s_lin[0][row][tx][1] + s_lin[1][row][tx][1];

    float s1 = g_aff[0], c1 = g_aff[1], w2c = g_aff[2], b2c = g_aff[3];
    float bn0 = fmaf(L0, s1, c1);
    float bn1 = fmaf(L1, s1, c1);
    float ac0 = fmaf(fmaxf(bn0, 0.0f), w2c, b2c);
    float ac1 = fmaf(fmaxf(bn1, 0.0f), w2c, b2c);
    float wgt0 = __fdividef(1.0f, 1.0f + __expf(-ac0));
    float wgt1 = __fdividef(1.0f, 1.0f + __expf(-ac1));
    float iw = __fdividef(1.0f, wgt0 + wgt1);

    float* op = out + (gbase * D_ + d) * HW_ + p;
#pragma unroll
    for (int j = 0; j < 4; j++) {
        op[j * (D_ * HW_)] = (wgt0 * v[0][j] + wgt1 * v[1][j]) * iw;
    }
}

// ---------------------------------------------------------------------------
// Launch
// ---------------------------------------------------------------------------
extern "C" void kernel_launch(void* const* d_in, const int* in_sizes, int n_in,
                              void* d_out, int out_size) {
    const float* ref_feature = (const float*)d_in[0];
    const float* src_features = (const float*)d_in[1];
    const float* ref_proj = (const float*)d_in[2];
    const float* src_projs = (const float*)d_in[3];
    const float* depth_hypos = (const float*)d_in[4];
    const float* w1 = (const float*)d_in[5];
    const float* bn_gamma = (const float*)d_in[6];
    const float* bn_beta = (const float*)d_in[7];
    const float* bn_mean = (const float*)d_in[8];
    const float* bn_var = (const float*)d_in[9];
    const float* w2 = (const float*)d_in[10];
    const float* b2 = (const float*)d_in[11];
    float* out = (float*)d_out;

    prep_all_kernel<<<(T2_ + 255) / 256, 256>>>(
        ref_feature, src_features, ref_proj, src_projs, w1, bn_gamma, bn_beta,
        bn_mean, bn_var, w2, b2);

    dim3 grid(W_ / 32, H_ / 4, D_);
    dim3 block(32, 8);
    fuse_kernel<<<grid, block>>>(depth_hypos, out);
}